// round 5
// baseline (speedup 1.0000x reference)
#include <cuda_runtime.h>
#include <math.h>
#include <stdint.h>

#define TT 2048
#define DIM 2048
#define NEXP 32
#define TOPK 4
#define INTER 1024
#define SHIN 2048
#define NA (TT*TOPK)
#define BM 128
#define MAXTILES (NA/BM + NEXP)   /* 96 */
#define PADS 36                   /* smem row stride in floats */

// ---------------- device scratch ----------------
__device__ int   g_topi[TT*TOPK];
__device__ float g_topw[TT*TOPK];
__device__ int   g_cnt[NEXP];
__device__ int   g_off[NEXP+1];
__device__ int   g_tok[NA];
__device__ float g_wt[NA];
__device__ int   g_tile_e[MAXTILES];
__device__ int   g_tile_r0[MAXTILES];
__device__ int   g_tile_n[MAXTILES];
__device__ int   g_ntiles;
__device__ float g_h[(size_t)NA*INTER];
__device__ float g_hs[(size_t)TT*SHIN];

// ---------------- helpers ----------------
__device__ __forceinline__ uint32_t smem_u32(const void* p) {
    uint32_t a;
    asm("{ .reg .u64 t; cvta.to.shared.u64 t, %1; cvt.u32.u64 %0, t; }" : "=r"(a) : "l"(p));
    return a;
}
__device__ __forceinline__ uint32_t f2tf(float f) {
    uint32_t r; asm("cvt.rna.tf32.f32 %0, %1;" : "=r"(r) : "f"(f)); return r;
}
__device__ __forceinline__ void cp16(uint32_t dst, const void* src) {
    asm volatile("cp.async.cg.shared.global [%0], [%1], 16;" :: "r"(dst), "l"(src));
}
#define CP_COMMIT() asm volatile("cp.async.commit_group;" ::: "memory")
template<int N>
__device__ __forceinline__ void cp_wait() {
    asm volatile("cp.async.wait_group %0;" :: "n"(N) : "memory");
}
__device__ __forceinline__ void mma8(float* c, const uint32_t* a, const uint32_t* b) {
    asm volatile("mma.sync.aligned.m16n8k8.row.col.f32.tf32.tf32.f32 "
        "{%0,%1,%2,%3}, {%4,%5,%6,%7}, {%8,%9}, {%0,%1,%2,%3};"
        : "+f"(c[0]), "+f"(c[1]), "+f"(c[2]), "+f"(c[3])
        : "r"(a[0]), "r"(a[1]), "r"(a[2]), "r"(a[3]), "r"(b[0]), "r"(b[1]));
}
__device__ __forceinline__ void ldsm4(uint32_t* r, uint32_t addr) {
    asm volatile("ldmatrix.sync.aligned.m8n8.x4.shared.b16 {%0,%1,%2,%3}, [%4];"
        : "=r"(r[0]), "=r"(r[1]), "=r"(r[2]), "=r"(r[3]) : "r"(addr));
}
__device__ __forceinline__ float silu_f(float v) { return v / (1.0f + __expf(-v)); }

// ---------------- kernel 0: zero counters ----------------
__global__ void k_zero() {
    if (threadIdx.x < NEXP) g_cnt[threadIdx.x] = 0;
}

// ---------------- kernel 1: gate (fp32 exact) ----------------
__global__ __launch_bounds__(128) void k_gate(const float* __restrict__ x,
                                              const float* __restrict__ gw) {
    __shared__ float sx[DIM];
    __shared__ float slog[NEXP];
    int t = blockIdx.x;
    const float* xr = x + (size_t)t * DIM;
    for (int i = threadIdx.x * 4; i < DIM; i += 128 * 4)
        *(float4*)(sx + i) = *(const float4*)(xr + i);
    __syncthreads();

    int e = threadIdx.x >> 2, part = threadIdx.x & 3;
    const float* wr = gw + (size_t)e * DIM;
    float s = 0.f;
    for (int k = part * 4; k < DIM; k += 16) {
        float4 a = *(const float4*)(sx + k);
        float4 b = *(const float4*)(wr + k);
        s += a.x * b.x + a.y * b.y + a.z * b.z + a.w * b.w;
    }
    s += __shfl_down_sync(0xffffffffu, s, 2, 4);
    s += __shfl_down_sync(0xffffffffu, s, 1, 4);
    if (part == 0) slog[e] = s;
    __syncthreads();

    if (threadIdx.x < 32) {
        float sc = slog[threadIdx.x];
        float m = sc;
        for (int o = 16; o; o >>= 1) m = fmaxf(m, __shfl_xor_sync(0xffffffffu, m, o));
        float p = expf(sc - m);
        float sum = p;
        for (int o = 16; o; o >>= 1) sum += __shfl_xor_sync(0xffffffffu, sum, o);
        float v = p / sum;
        for (int r = 0; r < TOPK; r++) {
            float mv = v;
            for (int o = 16; o; o >>= 1) mv = fmaxf(mv, __shfl_xor_sync(0xffffffffu, mv, o));
            unsigned bal = __ballot_sync(0xffffffffu, v == mv);
            int idx = __ffs(bal) - 1;
            if (threadIdx.x == 0) {
                g_topi[t * TOPK + r] = idx;
                g_topw[t * TOPK + r] = mv;
                atomicAdd(&g_cnt[idx], 1);
            }
            if (threadIdx.x == idx) v = -1.f;
        }
    }
}

// ---------------- kernel 2: offsets + tile map ----------------
__global__ void k_build() {
    if (threadIdx.x == 0) {
        int off = 0;
        for (int e = 0; e < NEXP; e++) { g_off[e] = off; off += g_cnt[e]; }
        g_off[NEXP] = off;
        int nt = 0;
        for (int e = 0; e < NEXP; e++) {
            int n = g_cnt[e], base = g_off[e];
            for (int r0 = 0; r0 < n; r0 += BM) {
                g_tile_e[nt] = e; g_tile_r0[nt] = base + r0;
                g_tile_n[nt] = min(BM, n - r0); nt++;
            }
        }
        g_ntiles = nt;
    }
}

// ---------------- kernel 3: parallel deterministic scatter ----------------
__global__ __launch_bounds__(256) void k_scatter() {
    int e = blockIdx.x, tid = threadIdx.x, w = tid >> 5, lane = tid & 31;
    __shared__ int wc[8];
    int t0 = w * 256;
    int cnt = 0;
    for (int i = 0; i < 8; i++) {
        int t = t0 + i * 32 + lane;
        bool f = false;
        #pragma unroll
        for (int k = 0; k < TOPK; k++) if (g_topi[t * TOPK + k] == e) f = true;
        cnt += __popc(__ballot_sync(0xffffffffu, f));
    }
    if (lane == 0) wc[w] = cnt;
    __syncthreads();
    int base = g_off[e];
    for (int ww = 0; ww < w; ww++) base += wc[ww];
    for (int i = 0; i < 8; i++) {
        int t = t0 + i * 32 + lane;
        float wt = 0.f; bool f = false;
        #pragma unroll
        for (int k = 0; k < TOPK; k++)
            if (g_topi[t * TOPK + k] == e) { f = true; wt = g_topw[t * TOPK + k]; }
        unsigned bal = __ballot_sync(0xffffffffu, f);
        int pos = base + __popc(bal & ((1u << lane) - 1u));
        if (f) { g_tok[pos] = t; g_wt[pos] = wt; }
        base += __popc(bal);
    }
}

// ---------------- up kernel: mma.sync tf32 + ldmatrix ---------------------
template<bool SHARED>
__global__ __launch_bounds__(256, 2) void k_up_mma(const float* __restrict__ x,
                                                   const float* __restrict__ w1,
                                                   const float* __restrict__ w3) {
    constexpr int NI = SHARED ? SHIN : INTER;
    constexpr int KC = 32;
    constexpr int NCH = DIM / KC;             // 64
    constexpr int ATILE = BM * PADS;          // floats
    constexpr int STAGE = 2 * ATILE;

    extern __shared__ float sm[];
    __shared__ int s_tok[BM];

    int tile = blockIdx.x;
    int e = 0, r0, nvalid = BM;
    if (!SHARED) {
        if (tile >= g_ntiles) return;
        e = g_tile_e[tile]; r0 = g_tile_r0[tile]; nvalid = g_tile_n[tile];
    } else r0 = tile * BM;

    int tid = threadIdx.x, wid = tid >> 5, lane = tid & 31;
    int jblk = blockIdx.y * 64;
    int wm = wid & 3, wn = wid >> 2;          // 4 x 2 warps
    int gq = lane >> 2, cq = lane & 3;

    if (tid < BM)
        s_tok[tid] = SHARED ? (r0 + tid) : g_tok[r0 + min(tid, nvalid - 1)];
    __syncthreads();

    const float* gp[8];
    uint32_t so[8];
    uint32_t smu = smem_u32(sm);
    #pragma unroll
    for (int j = 0; j < 8; j++) {
        int id = tid + j * 256;
        int m = id >> 10;
        int r = (id & 1023) >> 3;
        int s = id & 7;
        so[j] = (uint32_t)(m * ATILE + r * PADS + s * 4);
        if (m == 0) gp[j] = x + (size_t)s_tok[r] * DIM + s * 4;
        else if (r < 64) gp[j] = w1 + ((size_t)e * NI + jblk + r) * DIM + s * 4;
        else             gp[j] = w3 + ((size_t)e * NI + jblk + (r - 64)) * DIM + s * 4;
    }

    float acc1[2][4][4], acc3[2][4][4];
    #pragma unroll
    for (int i = 0; i < 2; i++)
        #pragma unroll
        for (int j = 0; j < 4; j++)
            #pragma unroll
            for (int q = 0; q < 4; q++) { acc1[i][j][q] = 0.f; acc3[i][j][q] = 0.f; }

    // ldmatrix lane offsets (bytes)
    uint32_t aoff = (uint32_t)(((lane & 15) * PADS + ((lane & 16) ? 4 : 0)) * 4);
    uint32_t boff = (uint32_t)((((lane & 7) + ((lane & 16) ? 8 : 0)) * PADS
                               + ((lane & 8) ? 4 : 0)) * 4);

    #pragma unroll
    for (int j = 0; j < 8; j++) cp16((smu + so[j] * 4), gp[j]);
    CP_COMMIT();

    for (int c = 0; c < NCH; c++) {
        int st = c & 1;
        if (c + 1 < NCH) {
            int kb = (c + 1) * KC;
            #pragma unroll
            for (int j = 0; j < 8; j++)
                cp16((smu + ((st ^ 1) * STAGE + so[j]) * 4), gp[j] + kb);
            CP_COMMIT();
            cp_wait<1>();
        } else cp_wait<0>();
        __syncthreads();

        // in-place fp32 -> tf32 conversion of stage st
        float* stf = sm + st * STAGE;
        #pragma unroll
        for (int j = 0; j < 8; j++) {
            float4 v = *(float4*)(stf + so[j]);
            uint4 t;
            t.x = f2tf(v.x); t.y = f2tf(v.y); t.z = f2tf(v.z); t.w = f2tf(v.w);
            *(uint4*)(stf + so[j]) = t;
        }
        __syncthreads();

        uint32_t stA = smu + (uint32_t)(st * STAGE) * 4;
        uint32_t stB = stA + (uint32_t)ATILE * 4;

        #pragma unroll
        for (int ks = 0; ks < 4; ks++) {
            int kb = ks * 8;
            uint32_t a[2][4];
            #pragma unroll
            for (int i = 0; i < 2; i++)
                ldsm4(a[i], stA + (uint32_t)(((wm * 32 + i * 16) * PADS + kb) * 4) + aoff);
            uint32_t b1[2][4], b3[2][4];
            #pragma unroll
            for (int j2 = 0; j2 < 2; j2++) {
                int nc0 = wn * 32 + j2 * 16;
                ldsm4(b1[j2], stB + (uint32_t)((nc0 * PADS + kb) * 4) + boff);
                ldsm4(b3[j2], stB + (uint32_t)(((64 + nc0) * PADS + kb) * 4) + boff);
            }
            #pragma unroll
            for (int i = 0; i < 2; i++)
                #pragma unroll
                for (int j2 = 0; j2 < 2; j2++) {
                    mma8(acc1[i][j2 * 2 + 0], a[i], b1[j2] + 0);
                    mma8(acc1[i][j2 * 2 + 1], a[i], b1[j2] + 2);
                    mma8(acc3[i][j2 * 2 + 0], a[i], b3[j2] + 0);
                    mma8(acc3[i][j2 * 2 + 1], a[i], b3[j2] + 2);
                }
        }
        __syncthreads();
    }

    #pragma unroll
    for (int i = 0; i < 2; i++) {
        int rbase = wm * 32 + i * 16 + gq;
        #pragma unroll
        for (int j = 0; j < 4; j++) {
            int col = jblk + wn * 32 + j * 8 + 2 * cq;
            if (rbase < nvalid) {
                float2 o;
                o.x = silu_f(acc1[i][j][0]) * acc3[i][j][0];
                o.y = silu_f(acc1[i][j][1]) * acc3[i][j][1];
                float* dst = SHARED ? (g_hs + (size_t)(r0 + rbase) * SHIN + col)
                                    : (g_h  + (size_t)(r0 + rbase) * INTER + col);
                *(float2*)dst = o;
            }
            if (rbase + 8 < nvalid) {
                float2 o;
                o.x = silu_f(acc1[i][j][2]) * acc3[i][j][2];
                o.y = silu_f(acc1[i][j][3]) * acc3[i][j][3];
                float* dst = SHARED ? (g_hs + (size_t)(r0 + rbase + 8) * SHIN + col)
                                    : (g_h  + (size_t)(r0 + rbase + 8) * INTER + col);
                *(float2*)dst = o;
            }
        }
    }
}

// ---------------- down kernel: mma.sync tf32 + ldmatrix -------------------
template<bool SHARED>
__global__ __launch_bounds__(256, 2) void k_down_mma(const float* __restrict__ w2,
                                                     float* __restrict__ out) {
    constexpr int KD = SHARED ? SHIN : INTER;
    constexpr int KC = 32;
    constexpr int NCH = KD / KC;
    constexpr int ATILE = BM * PADS;
    constexpr int STAGE = 2 * ATILE;

    extern __shared__ float sm[];
    __shared__ int   s_tok[BM];
    __shared__ float s_wtv[BM];

    int tile = blockIdx.x;
    int e = 0, r0, nvalid = BM;
    if (!SHARED) {
        if (tile >= g_ntiles) return;
        e = g_tile_e[tile]; r0 = g_tile_r0[tile]; nvalid = g_tile_n[tile];
    } else r0 = tile * BM;

    int tid = threadIdx.x, wid = tid >> 5, lane = tid & 31;
    int dblk = blockIdx.y * 128;
    int wm = wid & 3, wn = wid >> 2;
    int gq = lane >> 2, cq = lane & 3;

    if (tid < BM) {
        if (SHARED) { s_tok[tid] = r0 + tid; s_wtv[tid] = 1.f; }
        else {
            int ok = tid < nvalid;
            s_tok[tid] = ok ? g_tok[r0 + tid] : 0;
            s_wtv[tid] = ok ? g_wt[r0 + tid]  : 0.f;
        }
    }
    __syncthreads();

    const float* gp[8];
    uint32_t so[8];
    uint32_t smu = smem_u32(sm);
    #pragma unroll
    for (int j = 0; j < 8; j++) {
        int id = tid + j * 256;
        int m = id >> 10;
        int r = (id & 1023) >> 3;
        int s = id & 7;
        so[j] = (uint32_t)(m * ATILE + r * PADS + s * 4);
        if (m == 0) gp[j] = SHARED ? (g_hs + (size_t)(r0 + r) * SHIN + s * 4)
                                   : (g_h + (size_t)min(r0 + r, NA - 1) * INTER + s * 4);
        else        gp[j] = w2 + ((size_t)e * DIM + dblk + r) * KD + s * 4;
    }

    float acc[2][8][4];
    #pragma unroll
    for (int i = 0; i < 2; i++)
        #pragma unroll
        for (int j = 0; j < 8; j++)
            #pragma unroll
            for (int q = 0; q < 4; q++) acc[i][j][q] = 0.f;

    uint32_t aoff = (uint32_t)(((lane & 15) * PADS + ((lane & 16) ? 4 : 0)) * 4);
    uint32_t boff = (uint32_t)((((lane & 7) + ((lane & 16) ? 8 : 0)) * PADS
                               + ((lane & 8) ? 4 : 0)) * 4);

    #pragma unroll
    for (int j = 0; j < 8; j++) cp16((smu + so[j] * 4), gp[j]);
    CP_COMMIT();

    for (int c = 0; c < NCH; c++) {
        int st = c & 1;
        if (c + 1 < NCH) {
            int kb = (c + 1) * KC;
            #pragma unroll
            for (int j = 0; j < 8; j++)
                cp16((smu + ((st ^ 1) * STAGE + so[j]) * 4), gp[j] + kb);
            CP_COMMIT();
            cp_wait<1>();
        } else cp_wait<0>();
        __syncthreads();

        float* stf = sm + st * STAGE;
        #pragma unroll
        for (int j = 0; j < 8; j++) {
            float4 v = *(float4*)(stf + so[j]);
            uint4 t;
            t.x = f2tf(v.x); t.y = f2tf(v.y); t.z = f2tf(v.z); t.w = f2tf(v.w);
            *(uint4*)(stf + so[j]) = t;
        }
        __syncthreads();

        uint32_t stA = smu + (uint32_t)(st * STAGE) * 4;
        uint32_t stB = stA + (uint32_t)ATILE * 4;

        #pragma unroll
        for (int ks = 0; ks < 4; ks++) {
            int kb = ks * 8;
            uint32_t a[2][4];
            #pragma unroll
            for (int i = 0; i < 2; i++)
                ldsm4(a[i], stA + (uint32_t)(((wm * 32 + i * 16) * PADS + kb) * 4) + aoff);
            uint32_t b[4][4];
            #pragma unroll
            for (int j2 = 0; j2 < 4; j2++)
                ldsm4(b[j2], stB + (uint32_t)(((wn * 64 + j2 * 16) * PADS + kb) * 4) + boff);
            #pragma unroll
            for (int i = 0; i < 2; i++)
                #pragma unroll
                for (int j2 = 0; j2 < 4; j2++) {
                    mma8(acc[i][j2 * 2 + 0], a[i], b[j2] + 0);
                    mma8(acc[i][j2 * 2 + 1], a[i], b[j2] + 2);
                }
        }
        __syncthreads();
    }

    #pragma unroll
    for (int i = 0; i < 2; i++) {
        int rbase = wm * 32 + i * 16 + gq;
        #pragma unroll
        for (int j = 0; j < 8; j++) {
            int col = dblk + wn * 64 + j * 8 + 2 * cq;
            #pragma unroll
            for (int half = 0; half < 2; half++) {
                int r = rbase + half * 8;
                if (r >= nvalid) continue;
                int tok = s_tok[r];
                float wt = s_wtv[r];
                float* dst = out + (size_t)tok * DIM + col;
                float v0 = acc[i][j][half * 2 + 0];
                float v1 = acc[i][j][half * 2 + 1];
                if (SHARED) {
                    float2 o; o.x = v0; o.y = v1;
                    *(float2*)dst = o;
                } else {
                    atomicAdd(dst + 0, v0 * wt);
                    atomicAdd(dst + 1, v1 * wt);
                }
            }
        }
    }
}

// ---------------- launch ----------------
extern "C" void kernel_launch(void* const* d_in, const int* in_sizes, int n_in,
                              void* d_out, int out_size) {
    const float* x   = (const float*)d_in[0];
    const float* gw  = (const float*)d_in[1];
    const float* w1  = (const float*)d_in[2];
    const float* w2  = (const float*)d_in[3];
    const float* w3  = (const float*)d_in[4];
    const float* sw1 = (const float*)d_in[5];
    const float* sw2 = (const float*)d_in[6];
    const float* sw3 = (const float*)d_in[7];
    float* out = (float*)d_out;

    const int smBytes = 2 * 2 * BM * PADS * 4;   // 73728
    cudaFuncSetAttribute((const void*)k_up_mma<false>,   cudaFuncAttributeMaxDynamicSharedMemorySize, smBytes);
    cudaFuncSetAttribute((const void*)k_up_mma<true>,    cudaFuncAttributeMaxDynamicSharedMemorySize, smBytes);
    cudaFuncSetAttribute((const void*)k_down_mma<false>, cudaFuncAttributeMaxDynamicSharedMemorySize, smBytes);
    cudaFuncSetAttribute((const void*)k_down_mma<true>,  cudaFuncAttributeMaxDynamicSharedMemorySize, smBytes);

    k_zero<<<1, 32>>>();
    k_gate<<<TT, 128>>>(x, gw);
    k_build<<<1, 1>>>();
    k_scatter<<<NEXP, 256>>>();

    k_up_mma<false><<<dim3(MAXTILES, INTER / 64), 256, smBytes>>>(x, w1, w3);
    k_up_mma<true><<<dim3(TT / BM, SHIN / 64), 256, smBytes>>>(x, sw1, sw3);

    k_down_mma<true><<<dim3(TT / BM, DIM / 128), 256, smBytes>>>(sw2, out);
    k_down_mma<false><<<dim3(MAXTILES, DIM / 128), 256, smBytes>>>(w2, out);
}